// round 14
// baseline (speedup 1.0000x reference)
#include <cuda_runtime.h>
#include <cstdint>

// Fixed shapes: x,y float32 (4,4096,6)
#define BB 4
#define NN 4096
#define NPTS (BB*NN)
#define NBLK 128                      // k_pre grid (co-resident for grid barrier)
#define LOG2E 1.4426950408889634f
#define LN2F  0.6931471805599453f
#define EPS2  1e-4f
#define BLOG  (-8.317766166719343f)   // -log(4096)
#define EBLOG (2.44140625e-4f)        // exp(BLOG)
#define POS_INF (__int_as_float(0x7f800000))
#define NEG_INF (__int_as_float(0xff800000))
#define PBUF (8*NN*8)                 // floats per P buffer (pair-interleaved, 32B/j)
#define NCHUNK 16

// ---- f32x2 packed-math helpers ----
#define FMA2(d,a,b,c) asm("fma.rn.f32x2 %0, %1, %2, %3;" : "=l"(d) : "l"(a), "l"(b), "l"(c))
__device__ __forceinline__ unsigned long long pack2(float lo, float hi) {
    unsigned long long d;
    asm("mov.b64 %0, {%1, %2};" : "=l"(d) : "r"(__float_as_uint(lo)), "r"(__float_as_uint(hi)));
    return d;
}
__device__ __forceinline__ void unpack2(float& lo, float& hi, unsigned long long d) {
    unsigned int a, b;
    asm("mov.b64 {%0, %1}, %2;" : "=r"(a), "=r"(b) : "l"(d));
    lo = __uint_as_float(a); hi = __uint_as_float(b);
}
__device__ __forceinline__ float ex2(float x) {
    float r; asm("ex2.approx.ftz.f32 %0, %1;" : "=f"(r) : "f"(x)); return r;
}
__device__ __forceinline__ float lg2(float x) {
    float r; asm("lg2.approx.ftz.f32 %0, %1;" : "=f"(r) : "f"(x)); return r;
}

// -------- device scratch --------
__device__ __align__(16) float d_U[NPTS*8];
__device__ __align__(16) float d_V[NPTS*8];
__device__ __align__(16) float d_Pbuf[2*PBUF];
__device__ float d_f[2][NPTS];
__device__ float d_g[2][NPTS];
__device__ float d_M0[8*32];
__device__ float d_M1[8*32];
__device__ float d_red[NBLK][16];
__device__ float d_osum[NBLK];
__device__ __align__(16) float2 d_part[32768*NCHUNK];
__device__ unsigned d_gen[4];
__device__ unsigned d_cnt[4];

// -------- software grid barrier (NBLK blocks co-resident) --------
__device__ __forceinline__ void grid_barrier(int k) {
    __syncthreads();
    if (threadIdx.x == 0) {
        __threadfence();
        unsigned g = d_gen[k];
        unsigned t = atomicAdd(&d_cnt[k], 1);
        if (t == NBLK - 1) {
            d_cnt[k] = 0;
            __threadfence();
            atomicExch(&d_gen[k], g + 1);
        } else {
            while (*((volatile unsigned*)&d_gen[k]) == g) { }
        }
        __threadfence();
    }
    __syncthreads();
}

__device__ __forceinline__ void reduce28_atomic(const float* acc, float* gdst) {
    int lane = threadIdx.x & 31;
    float mine = 0.f;
    #pragma unroll
    for (int c = 0; c < 28; ++c) {
        float v = acc[c];
        #pragma unroll
        for (int o = 16; o; o >>= 1) v += __shfl_xor_sync(0xffffffffu, v, o);
        if (lane == c) mine = v;
    }
    if (lane < 28) atomicAdd(gdst + lane, mine);
}

__device__ __forceinline__ float eval_poly(const float* __restrict__ M, const float* u) {
    float m[28];
    #pragma unroll
    for (int c = 0; c < 28; ++c) m[c] = M[c];
    float S = m[0];
    int cnt = 7;
    #pragma unroll
    for (int k = 0; k < 6; ++k) {
        float inner = m[1+k];
        inner = fmaf(0.5f * m[cnt], u[k], inner);
        cnt++;
        #pragma unroll
        for (int l = k+1; l < 6; ++l) { inner = fmaf(m[cnt], u[l], inner); cnt++; }
        S = fmaf(u[k], inner, S);
    }
    return S;
}

// pair-interleaved column format (32B/j): pair p holds
// [w0a w0b w1a w1b][w2a w2b w3a w3b][w4a w4b w5a w5b][ha hb pad pad]
__device__ __forceinline__ void write_pack_pair(float* segbase, int j, const float* u,
                                                float cw, float h2) {
    float* base = segbase + (size_t)(j >> 1)*16 + (j & 1);
    base[0]  = u[0]*cw;  base[2]  = u[1]*cw;
    base[4]  = u[2]*cw;  base[6]  = u[3]*cw;
    base[8]  = u[4]*cw;  base[10] = u[5]*cw;
    base[12] = h2;
}

// ============ k_pre: reduce -> build+moments0 -> poly0(+M1) -> poly1(+pack) ============
__global__ void __launch_bounds__(256) k_pre(const float* __restrict__ x,
                                             const float* __restrict__ y) {
    const int tid = threadIdx.x;
    const int p = blockIdx.x * 256 + tid;
    const int lane = tid & 31, warp = tid >> 5;
    const int q = (p < NPTS) ? p : p - NPTS;
    const bool isx = (p < NPTS);
    const int b = q >> 12;

    // ---------- Phase R: reduction of 13 stats ----------
    float rv[13];
    {
        const float* src = isx ? (x + (size_t)q*6) : (y + (size_t)q*6);
        float c[6];
        #pragma unroll
        for (int k = 0; k < 6; ++k) c[k] = src[k];
        rv[0] = c[0]*c[0] + c[1]*c[1] + c[2]*c[2];
        #pragma unroll
        for (int k = 0; k < 6; ++k) { rv[1+k] = c[k]; rv[7+k] = c[k]; }
    }
    #pragma unroll
    for (int o = 16; o; o >>= 1) {
        rv[0] = fmaxf(rv[0], __shfl_xor_sync(0xffffffffu, rv[0], o));
        #pragma unroll
        for (int k = 1; k <= 6; ++k) rv[k] = fminf(rv[k], __shfl_xor_sync(0xffffffffu, rv[k], o));
        #pragma unroll
        for (int k = 7; k <= 12; ++k) rv[k] = fmaxf(rv[k], __shfl_xor_sync(0xffffffffu, rv[k], o));
    }
    __shared__ float swr[8][13];
    if (lane == 0) {
        #pragma unroll
        for (int k = 0; k < 13; ++k) swr[warp][k] = rv[k];
    }
    if (blockIdx.x == 0) { d_M0[tid] = 0.f; d_M1[tid] = 0.f; if (tid < NBLK) d_osum[tid] = 0.f; }
    __syncthreads();
    if (tid == 0) {
        float a[13];
        #pragma unroll
        for (int k = 0; k < 13; ++k) a[k] = swr[0][k];
        for (int w = 1; w < 8; ++w) {
            a[0] = fmaxf(a[0], swr[w][0]);
            #pragma unroll
            for (int k = 1; k <= 6; ++k) a[k] = fminf(a[k], swr[w][k]);
            #pragma unroll
            for (int k = 7; k <= 12; ++k) a[k] = fmaxf(a[k], swr[w][k]);
        }
        #pragma unroll
        for (int k = 0; k < 13; ++k) d_red[blockIdx.x][k] = a[k];
    }
    grid_barrier(0);

    __shared__ float sg[128*13];
    if (tid < 128) {
        #pragma unroll
        for (int k = 0; k < 13; ++k) sg[tid*13 + k] = d_red[tid][k];
    }
    __syncthreads();
    for (int s = 64; s >= 1; s >>= 1) {
        if (tid < s) {
            sg[tid*13+0] = fmaxf(sg[tid*13+0], sg[(tid+s)*13+0]);
            #pragma unroll
            for (int k = 1; k <= 6; ++k) sg[tid*13+k] = fminf(sg[tid*13+k], sg[(tid+s)*13+k]);
            #pragma unroll
            for (int k = 7; k <= 12; ++k) sg[tid*13+k] = fmaxf(sg[tid*13+k], sg[(tid+s)*13+k]);
        }
        __syncthreads();
    }
    const float s_scale = 1.f / (sqrtf(sg[0]) + 1e-6f);
    float eps1;
    {
        float e = 0.f;
        #pragma unroll
        for (int k = 0; k < 6; ++k) { float d = sg[7+k] - sg[1+k]; e += d * d; }
        eps1 = e;
    }
    const float inv_e1 = 1.f / eps1;

    // ---------- Phase B: build U/V + stage-0 moments ----------
    float u[6], sq;
    {
        const float* src = isx ? (x + (size_t)q*6) : (y + (size_t)q*6);
        float* dst = isx ? (d_U + (size_t)q*8) : (d_V + (size_t)q*8);
        u[0] = src[0]*s_scale; u[1] = src[1]*s_scale; u[2] = src[2]*s_scale;
        u[3] = 0.1f * fminf(fmaxf(src[3], 0.f), 1.f);
        u[4] = 0.1f * fminf(fmaxf(src[4], 0.f), 1.f);
        u[5] = 0.1f * fminf(fmaxf(src[5], 0.f), 1.f);
        sq = u[0]*u[0]+u[1]*u[1]+u[2]*u[2]+u[3]*u[3]+u[4]*u[4]+u[5]*u[5];
        reinterpret_cast<float4*>(dst)[0] = make_float4(u[0], u[1], u[2], u[3]);
        reinterpret_cast<float4*>(dst)[1] = make_float4(u[4], u[5], sq, 0.f);
    }
    float w6[6];
    #pragma unroll
    for (int k = 0; k < 6; ++k) w6[k] = 2.f * u[k] * inv_e1;
    {
        int seg0 = (isx ? 4 : 0) + b;
        float om = ex2(LOG2E * ((0.f - sq) * inv_e1 + BLOG));
        float acc[28];
        acc[0] = om;
        #pragma unroll
        for (int k = 0; k < 6; ++k) acc[1+k] = om * w6[k];
        int cnt = 7;
        #pragma unroll
        for (int k = 0; k < 6; ++k)
            #pragma unroll
            for (int l = k; l < 6; ++l) acc[cnt++] = acc[1+k] * w6[l];
        reduce28_atomic(acc, d_M0 + seg0*32);
    }
    grid_barrier(1);

    // ---------- Phase P0: f0/g0 + stage-1 moments ----------
    const int dir = isx ? 0 : 1;
    {
        int rowseg = dir*4 + b;
        float S = eval_poly(d_M0 + rowseg*32, u);
        float val = sq - eps1 * (LN2F * lg2(S));
        if (dir == 0) d_f[0][q] = val; else d_g[0][q] = val;
        float om = __fdividef(EBLOG, S);
        int colseg = (dir^1)*4 + b;
        float acc[28];
        acc[0] = om;
        #pragma unroll
        for (int k = 0; k < 6; ++k) acc[1+k] = om * w6[k];
        int cnt = 7;
        #pragma unroll
        for (int k = 0; k < 6; ++k)
            #pragma unroll
            for (int l = k; l < 6; ++l) acc[cnt++] = acc[1+k] * w6[l];
        reduce28_atomic(acc, d_M1 + colseg*32);
    }
    grid_barrier(2);

    // ---------- Phase P1: f1/g1 + pack eps2 columns -> Pbuf[0] ----------
    {
        int rowseg = dir*4 + b;
        float S = eval_poly(d_M1 + rowseg*32, u);
        float val = sq - eps1 * (LN2F * lg2(S));
        float prev = (dir == 0) ? d_f[0][q] : d_g[0][q];
        float res = 0.5f * (prev + val);
        if (dir == 0) d_f[1][q] = res; else d_g[1][q] = res;

        int colseg = (dir^1)*4 + b;
        float cw = 2.f * LOG2E / EPS2;
        float h2 = LOG2E * BLOG + (res - sq) * (LOG2E / EPS2);
        write_pack_pair(d_Pbuf + (size_t)colseg*NN*8, q & (NN-1), u, cw, h2);
    }
}

// ============ eps2 main: quad-j via SMEM stage, 2 rows/thread, 128-thread blocks ============
// grid = (64 rowtiles, 8 segs, 16 jchunks), block 128 (4 warps, each warp 32 j-pairs
// = 16 quads). Block covers 64 rows; each thread 2 rows (lane, lane+32).
// Per quad: two FMA2 dot chains per row (4 j's), hi = max of 4, ONE streaming merge.
// 2 rows/thread halves U register footprint (24 regs) -> 9 blocks/SM resident.
__global__ void __launch_bounds__(128, 9) k_main(int srcpp) {
    const int seg = blockIdx.y;
    const int b = seg & 3;
    const int dir = seg >> 2;
    const float* Rows = (dir ? d_V : d_U) + (size_t)b*NN*8;
    const float* Pin  = d_Pbuf + (size_t)srcpp*PBUF + (size_t)seg*NN*8;

    const int lane = threadIdx.x & 31;
    const int warp = threadIdx.x >> 5;      // 0..3
    const int rowbase = blockIdx.x * 64;

    __shared__ __align__(16) float sP[4][512];    // 4 warps x 32 pairs x 64B

    // stage this warp's 32 pairs (2KB) into shared: 128 float4, 4 per lane
    {
        const float4* src = reinterpret_cast<const float4*>(Pin)
                            + ((size_t)blockIdx.z*128 + (size_t)warp*32)*4;
        float4* dst = reinterpret_cast<float4*>(&sP[warp][0]);
        #pragma unroll
        for (int i = 0; i < 4; ++i) dst[lane + 32*i] = src[lane + 32*i];
    }

    // 2 rows per thread (lane, +32), each duplicated into f32x2 chains
    unsigned long long U[2][6];
    #pragma unroll
    for (int p = 0; p < 2; ++p) {
        const float4* ra = reinterpret_cast<const float4*>(Rows + (size_t)(rowbase + lane + 32*p)*8);
        float4 a0 = ra[0], a1 = ra[1];
        U[p][0] = pack2(a0.x, a0.x); U[p][1] = pack2(a0.y, a0.y); U[p][2] = pack2(a0.z, a0.z);
        U[p][3] = pack2(a0.w, a0.w); U[p][4] = pack2(a1.x, a1.x); U[p][5] = pack2(a1.y, a1.y);
    }
    __syncwarp();

    float m[2], s[2];
    #pragma unroll
    for (int p = 0; p < 2; ++p) { m[p] = NEG_INF; s[p] = 0.f; }

    const float* W = &sP[warp][0];
    #pragma unroll 2
    for (int it = 0; it < 16; ++it) {
        const float* Wp = W + it*32;            // two consecutive pair records (128B)
        ulonglong2 q0 = *reinterpret_cast<const ulonglong2*>(Wp + 0);
        ulonglong2 q1 = *reinterpret_cast<const ulonglong2*>(Wp + 4);
        ulonglong2 q2 = *reinterpret_cast<const ulonglong2*>(Wp + 8);
        unsigned long long hp = *reinterpret_cast<const unsigned long long*>(Wp + 12);
        ulonglong2 r0 = *reinterpret_cast<const ulonglong2*>(Wp + 16);
        ulonglong2 r1 = *reinterpret_cast<const ulonglong2*>(Wp + 20);
        ulonglong2 r2 = *reinterpret_cast<const ulonglong2*>(Wp + 24);
        unsigned long long hq = *reinterpret_cast<const unsigned long long*>(Wp + 28);
        #pragma unroll
        for (int p = 0; p < 2; ++p) {
            unsigned long long A, B;
            FMA2(A, U[p][0], q0.x, hp);     FMA2(B, U[p][0], r0.x, hq);
            FMA2(A, U[p][1], q0.y, A);      FMA2(B, U[p][1], r0.y, B);
            FMA2(A, U[p][2], q1.x, A);      FMA2(B, U[p][2], r1.x, B);
            FMA2(A, U[p][3], q1.y, A);      FMA2(B, U[p][3], r1.y, B);
            FMA2(A, U[p][4], q2.x, A);      FMA2(B, U[p][4], r2.x, B);
            FMA2(A, U[p][5], q2.y, A);      FMA2(B, U[p][5], r2.y, B);
            // hi of quad -> single streaming logsumexp merge
            float x1, x2, x3, x4;
            unpack2(x1, x2, A); unpack2(x3, x4, B);
            float hi = fmaxf(fmaxf(x1, x2), fmaxf(x3, x4));
            float d  = hi - m[p];
            float e  = ex2(-fabsf(d));
            bool up_ = d > 0.f;
            s[p] = up_ ? fmaf(s[p], e, 1.f) : (s[p] + e);
            m[p] = fmaxf(m[p], hi);
        }
    }

    __shared__ float shA[4][64];
    __shared__ float shB[4][64];
    #pragma unroll
    for (int p = 0; p < 2; ++p) {
        shA[warp][lane + 32*p] = m[p];
        shB[warp][lane + 32*p] = s[p];
    }
    __syncthreads();

    if (threadIdx.x < 64) {
        const int t = threadIdx.x;          // 0..63, one row each
        float M = shA[0][t];
        #pragma unroll
        for (int w = 1; w < 4; ++w) M = fmaxf(M, shA[w][t]);
        float S = 0.f;
        #pragma unroll
        for (int w = 0; w < 4; ++w) S += shB[w][t] * ex2(shA[w][t] - M);
        d_part[((size_t)(seg << 12) + rowbase + t)*NCHUNK + blockIdx.z] = make_float2(M, S);
    }
}

// ============ merge partials -> potential update (+ next pack | + final partial sum) ============
template<bool HASNEXT>
__global__ void __launch_bounds__(256) k_merge(int cur, int dstpp, float alpha, float beta) {
    const int p = blockIdx.x * 256 + threadIdx.x;    // 0..32767
    const int seg = p >> 12;
    const int r = p & 4095;
    const int dir = seg >> 2;
    const int b = seg & 3;
    const int q = b*NN + r;

    float2 c[NCHUNK];
    #pragma unroll
    for (int k = 0; k < NCHUNK; ++k) c[k] = d_part[(size_t)p*NCHUNK + k];
    float M = c[0].x;
    #pragma unroll
    for (int k = 1; k < NCHUNK; ++k) M = fmaxf(M, c[k].x);
    float S = 0.f;
    #pragma unroll
    for (int k = 0; k < NCHUNK; ++k) S += c[k].y * ex2(c[k].x - M);

    const float* src = (dir ? d_V : d_U) + (size_t)q*8;
    float sq = src[6];
    float val = sq - EPS2 * LN2F * (M + lg2(S));
    if (HASNEXT) {
        float fin = (dir ? d_g[cur][q] : d_f[cur][q]);
        float res = fmaf(alpha, fin, beta * val);
        if (dir == 0) d_f[cur^1][q] = res; else d_g[cur^1][q] = res;
        float u[6];
        u[0]=src[0]; u[1]=src[1]; u[2]=src[2]; u[3]=src[3]; u[4]=src[4]; u[5]=src[5];
        float cw = 2.f * LOG2E / EPS2;
        float h2 = LOG2E * BLOG + (res - sq) * (LOG2E / EPS2);
        write_pack_pair(d_Pbuf + (size_t)dstpp*PBUF + (size_t)((dir^1)*4 + b)*NN*8, r, u, cw, h2);
    } else {
        // final stage: pure softmin; deterministic block partial-sum
        float sum = val;
        #pragma unroll
        for (int o = 16; o; o >>= 1) sum += __shfl_xor_sync(0xffffffffu, sum, o);
        __shared__ float sw[8];
        int lane = threadIdx.x & 31, w = threadIdx.x >> 5;
        if (lane == 0) sw[w] = sum;
        __syncthreads();
        if (threadIdx.x == 0) {
            float t = 0.f;
            #pragma unroll
            for (int wi = 0; wi < 8; ++wi) t += sw[wi];
            d_osum[blockIdx.x] = t;
        }
    }
}

// ============ final: sum 128 block partials ============
__global__ void k_out(float* __restrict__ out) {
    const int tid = threadIdx.x;           // 128 threads
    float v = d_osum[tid];
    #pragma unroll
    for (int o = 16; o; o >>= 1) v += __shfl_xor_sync(0xffffffffu, v, o);
    __shared__ float sw[4];
    if ((tid & 31) == 0) sw[tid >> 5] = v;
    __syncthreads();
    if (tid == 0) out[0] = (sw[0] + sw[1] + sw[2] + sw[3]) * (10.f / (float)NPTS);
}

extern "C" void kernel_launch(void* const* d_in, const int* in_sizes, int n_in,
                              void* d_out, int out_size) {
    (void)in_sizes; (void)n_in; (void)out_size;
    const float* x = (const float*)d_in[0];
    const float* y = (const float*)d_in[1];
    float* out = (float*)d_out;

    dim3 gm(64, 8, NCHUNK);
    k_pre<<<NBLK, 256>>>(x, y);                        // f1/g1 + Pbuf[0]
    k_main<<<gm, 128>>>(0);                            // stage2 partials
    k_merge<true ><<<NBLK, 256>>>(1, 1, 0.5f, 0.5f);   // f2/g2 -> idx0, pack Pbuf[1]
    k_main<<<gm, 128>>>(1);                            // stage3 partials
    k_merge<false><<<NBLK, 256>>>(0, 0, 0.0f, 1.0f);   // f_new/g_new + block sums
    k_out<<<1, 128>>>(out);
}

// round 15
// speedup vs baseline: 1.0490x; 1.0490x over previous
#include <cuda_runtime.h>
#include <cstdint>

// Fixed shapes: x,y float32 (4,4096,6)
#define BB 4
#define NN 4096
#define NPTS (BB*NN)
#define NBLK 128                      // k_pre grid (co-resident for grid barrier)
#define LOG2E 1.4426950408889634f
#define LN2F  0.6931471805599453f
#define EPS2  1e-4f
#define BLOG  (-8.317766166719343f)   // -log(4096)
#define EBLOG (2.44140625e-4f)        // exp(BLOG)
#define POS_INF (__int_as_float(0x7f800000))
#define NEG_INF (__int_as_float(0xff800000))
#define PBUF (8*NN*8)                 // floats per P buffer (pair-interleaved, 32B/j)
#define NCHUNK 16

// ---- f32x2 packed-math helpers ----
#define FMA2(d,a,b,c) asm("fma.rn.f32x2 %0, %1, %2, %3;" : "=l"(d) : "l"(a), "l"(b), "l"(c))
__device__ __forceinline__ unsigned long long pack2(float lo, float hi) {
    unsigned long long d;
    asm("mov.b64 %0, {%1, %2};" : "=l"(d) : "r"(__float_as_uint(lo)), "r"(__float_as_uint(hi)));
    return d;
}
__device__ __forceinline__ void unpack2(float& lo, float& hi, unsigned long long d) {
    unsigned int a, b;
    asm("mov.b64 {%0, %1}, %2;" : "=r"(a), "=r"(b) : "l"(d));
    lo = __uint_as_float(a); hi = __uint_as_float(b);
}
__device__ __forceinline__ float ex2(float x) {
    float r; asm("ex2.approx.ftz.f32 %0, %1;" : "=f"(r) : "f"(x)); return r;
}
__device__ __forceinline__ float lg2(float x) {
    float r; asm("lg2.approx.ftz.f32 %0, %1;" : "=f"(r) : "f"(x)); return r;
}

// -------- device scratch --------
__device__ __align__(16) float d_U[NPTS*8];
__device__ __align__(16) float d_V[NPTS*8];
__device__ __align__(16) float d_Pbuf[2*PBUF];
__device__ float d_f[2][NPTS];
__device__ float d_g[2][NPTS];
__device__ float d_M0[8*32];
__device__ float d_M1[8*32];
__device__ float d_red[NBLK][16];
__device__ float d_osum[NBLK];
__device__ __align__(16) float2 d_part[32768*NCHUNK];
__device__ unsigned d_gen[4];
__device__ unsigned d_cnt[4];

// -------- software grid barrier (NBLK blocks co-resident) --------
__device__ __forceinline__ void grid_barrier(int k) {
    __syncthreads();
    if (threadIdx.x == 0) {
        __threadfence();
        unsigned g = d_gen[k];
        unsigned t = atomicAdd(&d_cnt[k], 1);
        if (t == NBLK - 1) {
            d_cnt[k] = 0;
            __threadfence();
            atomicExch(&d_gen[k], g + 1);
        } else {
            while (*((volatile unsigned*)&d_gen[k]) == g) { }
        }
        __threadfence();
    }
    __syncthreads();
}

__device__ __forceinline__ void reduce28_atomic(const float* acc, float* gdst) {
    int lane = threadIdx.x & 31;
    float mine = 0.f;
    #pragma unroll
    for (int c = 0; c < 28; ++c) {
        float v = acc[c];
        #pragma unroll
        for (int o = 16; o; o >>= 1) v += __shfl_xor_sync(0xffffffffu, v, o);
        if (lane == c) mine = v;
    }
    if (lane < 28) atomicAdd(gdst + lane, mine);
}

__device__ __forceinline__ float eval_poly(const float* __restrict__ M, const float* u) {
    float m[28];
    #pragma unroll
    for (int c = 0; c < 28; ++c) m[c] = M[c];
    float S = m[0];
    int cnt = 7;
    #pragma unroll
    for (int k = 0; k < 6; ++k) {
        float inner = m[1+k];
        inner = fmaf(0.5f * m[cnt], u[k], inner);
        cnt++;
        #pragma unroll
        for (int l = k+1; l < 6; ++l) { inner = fmaf(m[cnt], u[l], inner); cnt++; }
        S = fmaf(u[k], inner, S);
    }
    return S;
}

// pair-interleaved column format (32B/j): pair p holds
// [w0a w0b w1a w1b][w2a w2b w3a w3b][w4a w4b w5a w5b][ha hb pad pad]
__device__ __forceinline__ void write_pack_pair(float* segbase, int j, const float* u,
                                                float cw, float h2) {
    float* base = segbase + (size_t)(j >> 1)*16 + (j & 1);
    base[0]  = u[0]*cw;  base[2]  = u[1]*cw;
    base[4]  = u[2]*cw;  base[6]  = u[3]*cw;
    base[8]  = u[4]*cw;  base[10] = u[5]*cw;
    base[12] = h2;
}

// ============ k_pre: reduce -> build+moments0 -> poly0(+M1) -> poly1(+pack) ============
__global__ void __launch_bounds__(256) k_pre(const float* __restrict__ x,
                                             const float* __restrict__ y) {
    const int tid = threadIdx.x;
    const int p = blockIdx.x * 256 + tid;
    const int lane = tid & 31, warp = tid >> 5;
    const int q = (p < NPTS) ? p : p - NPTS;
    const bool isx = (p < NPTS);
    const int b = q >> 12;

    // ---------- Phase R: reduction of 13 stats ----------
    float rv[13];
    {
        const float* src = isx ? (x + (size_t)q*6) : (y + (size_t)q*6);
        float c[6];
        #pragma unroll
        for (int k = 0; k < 6; ++k) c[k] = src[k];
        rv[0] = c[0]*c[0] + c[1]*c[1] + c[2]*c[2];
        #pragma unroll
        for (int k = 0; k < 6; ++k) { rv[1+k] = c[k]; rv[7+k] = c[k]; }
    }
    #pragma unroll
    for (int o = 16; o; o >>= 1) {
        rv[0] = fmaxf(rv[0], __shfl_xor_sync(0xffffffffu, rv[0], o));
        #pragma unroll
        for (int k = 1; k <= 6; ++k) rv[k] = fminf(rv[k], __shfl_xor_sync(0xffffffffu, rv[k], o));
        #pragma unroll
        for (int k = 7; k <= 12; ++k) rv[k] = fmaxf(rv[k], __shfl_xor_sync(0xffffffffu, rv[k], o));
    }
    __shared__ float swr[8][13];
    if (lane == 0) {
        #pragma unroll
        for (int k = 0; k < 13; ++k) swr[warp][k] = rv[k];
    }
    if (blockIdx.x == 0) { d_M0[tid] = 0.f; d_M1[tid] = 0.f; if (tid < NBLK) d_osum[tid] = 0.f; }
    __syncthreads();
    if (tid == 0) {
        float a[13];
        #pragma unroll
        for (int k = 0; k < 13; ++k) a[k] = swr[0][k];
        for (int w = 1; w < 8; ++w) {
            a[0] = fmaxf(a[0], swr[w][0]);
            #pragma unroll
            for (int k = 1; k <= 6; ++k) a[k] = fminf(a[k], swr[w][k]);
            #pragma unroll
            for (int k = 7; k <= 12; ++k) a[k] = fmaxf(a[k], swr[w][k]);
        }
        #pragma unroll
        for (int k = 0; k < 13; ++k) d_red[blockIdx.x][k] = a[k];
    }
    grid_barrier(0);

    __shared__ float sg[128*13];
    if (tid < 128) {
        #pragma unroll
        for (int k = 0; k < 13; ++k) sg[tid*13 + k] = d_red[tid][k];
    }
    __syncthreads();
    for (int s = 64; s >= 1; s >>= 1) {
        if (tid < s) {
            sg[tid*13+0] = fmaxf(sg[tid*13+0], sg[(tid+s)*13+0]);
            #pragma unroll
            for (int k = 1; k <= 6; ++k) sg[tid*13+k] = fminf(sg[tid*13+k], sg[(tid+s)*13+k]);
            #pragma unroll
            for (int k = 7; k <= 12; ++k) sg[tid*13+k] = fmaxf(sg[tid*13+k], sg[(tid+s)*13+k]);
        }
        __syncthreads();
    }
    const float s_scale = 1.f / (sqrtf(sg[0]) + 1e-6f);
    float eps1;
    {
        float e = 0.f;
        #pragma unroll
        for (int k = 0; k < 6; ++k) { float d = sg[7+k] - sg[1+k]; e += d * d; }
        eps1 = e;
    }
    const float inv_e1 = 1.f / eps1;

    // ---------- Phase B: build U/V + stage-0 moments ----------
    float u[6], sq;
    {
        const float* src = isx ? (x + (size_t)q*6) : (y + (size_t)q*6);
        float* dst = isx ? (d_U + (size_t)q*8) : (d_V + (size_t)q*8);
        u[0] = src[0]*s_scale; u[1] = src[1]*s_scale; u[2] = src[2]*s_scale;
        u[3] = 0.1f * fminf(fmaxf(src[3], 0.f), 1.f);
        u[4] = 0.1f * fminf(fmaxf(src[4], 0.f), 1.f);
        u[5] = 0.1f * fminf(fmaxf(src[5], 0.f), 1.f);
        sq = u[0]*u[0]+u[1]*u[1]+u[2]*u[2]+u[3]*u[3]+u[4]*u[4]+u[5]*u[5];
        reinterpret_cast<float4*>(dst)[0] = make_float4(u[0], u[1], u[2], u[3]);
        reinterpret_cast<float4*>(dst)[1] = make_float4(u[4], u[5], sq, 0.f);
    }
    float w6[6];
    #pragma unroll
    for (int k = 0; k < 6; ++k) w6[k] = 2.f * u[k] * inv_e1;
    {
        int seg0 = (isx ? 4 : 0) + b;
        float om = ex2(LOG2E * ((0.f - sq) * inv_e1 + BLOG));
        float acc[28];
        acc[0] = om;
        #pragma unroll
        for (int k = 0; k < 6; ++k) acc[1+k] = om * w6[k];
        int cnt = 7;
        #pragma unroll
        for (int k = 0; k < 6; ++k)
            #pragma unroll
            for (int l = k; l < 6; ++l) acc[cnt++] = acc[1+k] * w6[l];
        reduce28_atomic(acc, d_M0 + seg0*32);
    }
    grid_barrier(1);

    // ---------- Phase P0: f0/g0 + stage-1 moments ----------
    const int dir = isx ? 0 : 1;
    {
        int rowseg = dir*4 + b;
        float S = eval_poly(d_M0 + rowseg*32, u);
        float val = sq - eps1 * (LN2F * lg2(S));
        if (dir == 0) d_f[0][q] = val; else d_g[0][q] = val;
        float om = __fdividef(EBLOG, S);
        int colseg = (dir^1)*4 + b;
        float acc[28];
        acc[0] = om;
        #pragma unroll
        for (int k = 0; k < 6; ++k) acc[1+k] = om * w6[k];
        int cnt = 7;
        #pragma unroll
        for (int k = 0; k < 6; ++k)
            #pragma unroll
            for (int l = k; l < 6; ++l) acc[cnt++] = acc[1+k] * w6[l];
        reduce28_atomic(acc, d_M1 + colseg*32);
    }
    grid_barrier(2);

    // ---------- Phase P1: f1/g1 + pack eps2 columns -> Pbuf[0] ----------
    {
        int rowseg = dir*4 + b;
        float S = eval_poly(d_M1 + rowseg*32, u);
        float val = sq - eps1 * (LN2F * lg2(S));
        float prev = (dir == 0) ? d_f[0][q] : d_g[0][q];
        float res = 0.5f * (prev + val);
        if (dir == 0) d_f[1][q] = res; else d_g[1][q] = res;

        int colseg = (dir^1)*4 + b;
        float cw = 2.f * LOG2E / EPS2;
        float h2 = LOG2E * BLOG + (res - sq) * (LOG2E / EPS2);
        write_pack_pair(d_Pbuf + (size_t)colseg*NN*8, q & (NN-1), u, cw, h2);
    }
}

// ============ eps2 main: quad-j via SMEM stage, 4 rows/thread, 128-thread blocks ============
// grid = (32 rowtiles, 8 segs, 16 jchunks), block 128 (4 warps, each warp 32 j-pairs
// = 16 quads). Same dataflow as R13 but the two pair-records of a quad are processed
// in SEQUENTIAL halves reusing one set of load temps, and regs are capped at 64
// (launch_bounds min 8 blocks) -> 32 resident warps/SM instead of 28.
__global__ void __launch_bounds__(128, 8) k_main(int srcpp) {
    const int seg = blockIdx.y;
    const int b = seg & 3;
    const int dir = seg >> 2;
    const float* Rows = (dir ? d_V : d_U) + (size_t)b*NN*8;
    const float* Pin  = d_Pbuf + (size_t)srcpp*PBUF + (size_t)seg*NN*8;

    const int lane = threadIdx.x & 31;
    const int warp = threadIdx.x >> 5;      // 0..3
    const int rowbase = blockIdx.x * 128;

    __shared__ __align__(16) float sP[4][512];    // 4 warps x 32 pairs x 64B

    // stage this warp's 32 pairs (2KB) into shared: 128 float4, 4 per lane
    {
        const float4* src = reinterpret_cast<const float4*>(Pin)
                            + ((size_t)blockIdx.z*128 + (size_t)warp*32)*4;
        float4* dst = reinterpret_cast<float4*>(&sP[warp][0]);
        #pragma unroll
        for (int i = 0; i < 4; ++i) dst[lane + 32*i] = src[lane + 32*i];
    }

    // 4 rows per thread (lane, +32, +64, +96), each duplicated into f32x2 chains
    unsigned long long U[4][6];
    #pragma unroll
    for (int p = 0; p < 4; ++p) {
        const float4* ra = reinterpret_cast<const float4*>(Rows + (size_t)(rowbase + lane + 32*p)*8);
        float4 a0 = ra[0], a1 = ra[1];
        U[p][0] = pack2(a0.x, a0.x); U[p][1] = pack2(a0.y, a0.y); U[p][2] = pack2(a0.z, a0.z);
        U[p][3] = pack2(a0.w, a0.w); U[p][4] = pack2(a1.x, a1.x); U[p][5] = pack2(a1.y, a1.y);
    }
    __syncwarp();

    float m[4], s[4];
    #pragma unroll
    for (int p = 0; p < 4; ++p) { m[p] = NEG_INF; s[p] = 0.f; }

    const float* W = &sP[warp][0];
    #pragma unroll 2
    for (int it = 0; it < 16; ++it) {
        const float* Wp = W + it*32;            // quad = two consecutive pair records
        unsigned long long A[4];
        {   // half 1: first pair record (j0,j1)
            ulonglong2 q0 = *reinterpret_cast<const ulonglong2*>(Wp + 0);
            ulonglong2 q1 = *reinterpret_cast<const ulonglong2*>(Wp + 4);
            ulonglong2 q2 = *reinterpret_cast<const ulonglong2*>(Wp + 8);
            unsigned long long hp = *reinterpret_cast<const unsigned long long*>(Wp + 12);
            #pragma unroll
            for (int p = 0; p < 4; ++p) {
                unsigned long long A_;
                FMA2(A_, U[p][0], q0.x, hp);
                FMA2(A_, U[p][1], q0.y, A_);
                FMA2(A_, U[p][2], q1.x, A_);
                FMA2(A_, U[p][3], q1.y, A_);
                FMA2(A_, U[p][4], q2.x, A_);
                FMA2(A_, U[p][5], q2.y, A_);
                A[p] = A_;
            }
        }
        {   // half 2: second pair record (j2,j3), then merge per row
            ulonglong2 q0 = *reinterpret_cast<const ulonglong2*>(Wp + 16);
            ulonglong2 q1 = *reinterpret_cast<const ulonglong2*>(Wp + 20);
            ulonglong2 q2 = *reinterpret_cast<const ulonglong2*>(Wp + 24);
            unsigned long long hp = *reinterpret_cast<const unsigned long long*>(Wp + 28);
            #pragma unroll
            for (int p = 0; p < 4; ++p) {
                unsigned long long B_;
                FMA2(B_, U[p][0], q0.x, hp);
                FMA2(B_, U[p][1], q0.y, B_);
                FMA2(B_, U[p][2], q1.x, B_);
                FMA2(B_, U[p][3], q1.y, B_);
                FMA2(B_, U[p][4], q2.x, B_);
                FMA2(B_, U[p][5], q2.y, B_);
                // hi of quad -> single streaming logsumexp merge
                float x1, x2, x3, x4;
                unpack2(x1, x2, A[p]); unpack2(x3, x4, B_);
                float hi = fmaxf(fmaxf(x1, x2), fmaxf(x3, x4));
                float d  = hi - m[p];
                float e  = ex2(-fabsf(d));
                bool up_ = d > 0.f;
                s[p] = up_ ? fmaf(s[p], e, 1.f) : (s[p] + e);
                m[p] = fmaxf(m[p], hi);
            }
        }
    }

    __shared__ float shA[4][128];
    __shared__ float shB[4][128];
    #pragma unroll
    for (int p = 0; p < 4; ++p) {
        shA[warp][lane + 32*p] = m[p];
        shB[warp][lane + 32*p] = s[p];
    }
    __syncthreads();

    {
        const int t = threadIdx.x;          // 0..127, one row each
        float M = shA[0][t];
        #pragma unroll
        for (int w = 1; w < 4; ++w) M = fmaxf(M, shA[w][t]);
        float S = 0.f;
        #pragma unroll
        for (int w = 0; w < 4; ++w) S += shB[w][t] * ex2(shA[w][t] - M);
        d_part[((size_t)(seg << 12) + rowbase + t)*NCHUNK + blockIdx.z] = make_float2(M, S);
    }
}

// ============ merge partials -> potential update (+ next pack | + final partial sum) ============
template<bool HASNEXT>
__global__ void __launch_bounds__(256) k_merge(int cur, int dstpp, float alpha, float beta) {
    const int p = blockIdx.x * 256 + threadIdx.x;    // 0..32767
    const int seg = p >> 12;
    const int r = p & 4095;
    const int dir = seg >> 2;
    const int b = seg & 3;
    const int q = b*NN + r;

    float2 c[NCHUNK];
    #pragma unroll
    for (int k = 0; k < NCHUNK; ++k) c[k] = d_part[(size_t)p*NCHUNK + k];
    float M = c[0].x;
    #pragma unroll
    for (int k = 1; k < NCHUNK; ++k) M = fmaxf(M, c[k].x);
    float S = 0.f;
    #pragma unroll
    for (int k = 0; k < NCHUNK; ++k) S += c[k].y * ex2(c[k].x - M);

    const float* src = (dir ? d_V : d_U) + (size_t)q*8;
    float sq = src[6];
    float val = sq - EPS2 * LN2F * (M + lg2(S));
    if (HASNEXT) {
        float fin = (dir ? d_g[cur][q] : d_f[cur][q]);
        float res = fmaf(alpha, fin, beta * val);
        if (dir == 0) d_f[cur^1][q] = res; else d_g[cur^1][q] = res;
        float u[6];
        u[0]=src[0]; u[1]=src[1]; u[2]=src[2]; u[3]=src[3]; u[4]=src[4]; u[5]=src[5];
        float cw = 2.f * LOG2E / EPS2;
        float h2 = LOG2E * BLOG + (res - sq) * (LOG2E / EPS2);
        write_pack_pair(d_Pbuf + (size_t)dstpp*PBUF + (size_t)((dir^1)*4 + b)*NN*8, r, u, cw, h2);
    } else {
        // final stage: pure softmin; deterministic block partial-sum
        float sum = val;
        #pragma unroll
        for (int o = 16; o; o >>= 1) sum += __shfl_xor_sync(0xffffffffu, sum, o);
        __shared__ float sw[8];
        int lane = threadIdx.x & 31, w = threadIdx.x >> 5;
        if (lane == 0) sw[w] = sum;
        __syncthreads();
        if (threadIdx.x == 0) {
            float t = 0.f;
            #pragma unroll
            for (int wi = 0; wi < 8; ++wi) t += sw[wi];
            d_osum[blockIdx.x] = t;
        }
    }
}

// ============ final: sum 128 block partials ============
__global__ void k_out(float* __restrict__ out) {
    const int tid = threadIdx.x;           // 128 threads
    float v = d_osum[tid];
    #pragma unroll
    for (int o = 16; o; o >>= 1) v += __shfl_xor_sync(0xffffffffu, v, o);
    __shared__ float sw[4];
    if ((tid & 31) == 0) sw[tid >> 5] = v;
    __syncthreads();
    if (tid == 0) out[0] = (sw[0] + sw[1] + sw[2] + sw[3]) * (10.f / (float)NPTS);
}

extern "C" void kernel_launch(void* const* d_in, const int* in_sizes, int n_in,
                              void* d_out, int out_size) {
    (void)in_sizes; (void)n_in; (void)out_size;
    const float* x = (const float*)d_in[0];
    const float* y = (const float*)d_in[1];
    float* out = (float*)d_out;

    dim3 gm(32, 8, NCHUNK);
    k_pre<<<NBLK, 256>>>(x, y);                        // f1/g1 + Pbuf[0]
    k_main<<<gm, 128>>>(0);                            // stage2 partials
    k_merge<true ><<<NBLK, 256>>>(1, 1, 0.5f, 0.5f);   // f2/g2 -> idx0, pack Pbuf[1]
    k_main<<<gm, 128>>>(1);                            // stage3 partials
    k_merge<false><<<NBLK, 256>>>(0, 0, 0.0f, 1.0f);   // f_new/g_new + block sums
    k_out<<<1, 128>>>(out);
}

// round 16
// speedup vs baseline: 1.0590x; 1.0095x over previous
#include <cuda_runtime.h>
#include <cstdint>

// Fixed shapes: x,y float32 (4,4096,6)
#define BB 4
#define NN 4096
#define NPTS (BB*NN)
#define NBLK 128                      // k_pre grid (co-resident for grid barrier)
#define LOG2E 1.4426950408889634f
#define LN2F  0.6931471805599453f
#define EPS2  1e-4f
#define BLOG  (-8.317766166719343f)   // -log(4096)
#define EBLOG (2.44140625e-4f)        // exp(BLOG)
#define POS_INF (__int_as_float(0x7f800000))
#define NEG_INF (__int_as_float(0xff800000))
#define PBUF (8*NN*8)                 // floats per P buffer (pair-interleaved, 32B/j)
#define NCHUNK 8

// ---- f32x2 packed-math helpers ----
#define FMA2(d,a,b,c) asm("fma.rn.f32x2 %0, %1, %2, %3;" : "=l"(d) : "l"(a), "l"(b), "l"(c))
__device__ __forceinline__ unsigned long long pack2(float lo, float hi) {
    unsigned long long d;
    asm("mov.b64 %0, {%1, %2};" : "=l"(d) : "r"(__float_as_uint(lo)), "r"(__float_as_uint(hi)));
    return d;
}
__device__ __forceinline__ void unpack2(float& lo, float& hi, unsigned long long d) {
    unsigned int a, b;
    asm("mov.b64 {%0, %1}, %2;" : "=r"(a), "=r"(b) : "l"(d));
    lo = __uint_as_float(a); hi = __uint_as_float(b);
}
__device__ __forceinline__ float ex2(float x) {
    float r; asm("ex2.approx.ftz.f32 %0, %1;" : "=f"(r) : "f"(x)); return r;
}
__device__ __forceinline__ float lg2(float x) {
    float r; asm("lg2.approx.ftz.f32 %0, %1;" : "=f"(r) : "f"(x)); return r;
}

// -------- device scratch --------
__device__ __align__(16) float d_U[NPTS*8];
__device__ __align__(16) float d_V[NPTS*8];
__device__ __align__(16) float d_Pbuf[2*PBUF];
__device__ float d_f[2][NPTS];
__device__ float d_g[2][NPTS];
__device__ float d_M0[8*32];
__device__ float d_M1[8*32];
__device__ float d_red[NBLK][16];
__device__ float d_osum[NBLK];
__device__ __align__(16) float2 d_part[32768*NCHUNK];
__device__ unsigned d_gen[4];
__device__ unsigned d_cnt[4];

// -------- software grid barrier (NBLK blocks co-resident) --------
__device__ __forceinline__ void grid_barrier(int k) {
    __syncthreads();
    if (threadIdx.x == 0) {
        __threadfence();
        unsigned g = d_gen[k];
        unsigned t = atomicAdd(&d_cnt[k], 1);
        if (t == NBLK - 1) {
            d_cnt[k] = 0;
            __threadfence();
            atomicExch(&d_gen[k], g + 1);
        } else {
            while (*((volatile unsigned*)&d_gen[k]) == g) { }
        }
        __threadfence();
    }
    __syncthreads();
}

__device__ __forceinline__ void reduce28_atomic(const float* acc, float* gdst) {
    int lane = threadIdx.x & 31;
    float mine = 0.f;
    #pragma unroll
    for (int c = 0; c < 28; ++c) {
        float v = acc[c];
        #pragma unroll
        for (int o = 16; o; o >>= 1) v += __shfl_xor_sync(0xffffffffu, v, o);
        if (lane == c) mine = v;
    }
    if (lane < 28) atomicAdd(gdst + lane, mine);
}

__device__ __forceinline__ float eval_poly(const float* __restrict__ M, const float* u) {
    float m[28];
    #pragma unroll
    for (int c = 0; c < 28; ++c) m[c] = M[c];
    float S = m[0];
    int cnt = 7;
    #pragma unroll
    for (int k = 0; k < 6; ++k) {
        float inner = m[1+k];
        inner = fmaf(0.5f * m[cnt], u[k], inner);
        cnt++;
        #pragma unroll
        for (int l = k+1; l < 6; ++l) { inner = fmaf(m[cnt], u[l], inner); cnt++; }
        S = fmaf(u[k], inner, S);
    }
    return S;
}

// pair-interleaved column format (32B/j): pair p holds
// [w0a w0b w1a w1b][w2a w2b w3a w3b][w4a w4b w5a w5b][ha hb pad pad]
__device__ __forceinline__ void write_pack_pair(float* segbase, int j, const float* u,
                                                float cw, float h2) {
    float* base = segbase + (size_t)(j >> 1)*16 + (j & 1);
    base[0]  = u[0]*cw;  base[2]  = u[1]*cw;
    base[4]  = u[2]*cw;  base[6]  = u[3]*cw;
    base[8]  = u[4]*cw;  base[10] = u[5]*cw;
    base[12] = h2;
}

// ============ k_pre: reduce -> build+moments0 -> poly0(+M1) -> poly1(+pack) ============
__global__ void __launch_bounds__(256) k_pre(const float* __restrict__ x,
                                             const float* __restrict__ y) {
    const int tid = threadIdx.x;
    const int p = blockIdx.x * 256 + tid;
    const int lane = tid & 31, warp = tid >> 5;
    const int q = (p < NPTS) ? p : p - NPTS;
    const bool isx = (p < NPTS);
    const int b = q >> 12;

    // ---------- Phase R: reduction of 13 stats ----------
    float rv[13];
    {
        const float* src = isx ? (x + (size_t)q*6) : (y + (size_t)q*6);
        float c[6];
        #pragma unroll
        for (int k = 0; k < 6; ++k) c[k] = src[k];
        rv[0] = c[0]*c[0] + c[1]*c[1] + c[2]*c[2];
        #pragma unroll
        for (int k = 0; k < 6; ++k) { rv[1+k] = c[k]; rv[7+k] = c[k]; }
    }
    #pragma unroll
    for (int o = 16; o; o >>= 1) {
        rv[0] = fmaxf(rv[0], __shfl_xor_sync(0xffffffffu, rv[0], o));
        #pragma unroll
        for (int k = 1; k <= 6; ++k) rv[k] = fminf(rv[k], __shfl_xor_sync(0xffffffffu, rv[k], o));
        #pragma unroll
        for (int k = 7; k <= 12; ++k) rv[k] = fmaxf(rv[k], __shfl_xor_sync(0xffffffffu, rv[k], o));
    }
    __shared__ float swr[8][13];
    if (lane == 0) {
        #pragma unroll
        for (int k = 0; k < 13; ++k) swr[warp][k] = rv[k];
    }
    if (blockIdx.x == 0) { d_M0[tid] = 0.f; d_M1[tid] = 0.f; if (tid < NBLK) d_osum[tid] = 0.f; }
    __syncthreads();
    if (tid == 0) {
        float a[13];
        #pragma unroll
        for (int k = 0; k < 13; ++k) a[k] = swr[0][k];
        for (int w = 1; w < 8; ++w) {
            a[0] = fmaxf(a[0], swr[w][0]);
            #pragma unroll
            for (int k = 1; k <= 6; ++k) a[k] = fminf(a[k], swr[w][k]);
            #pragma unroll
            for (int k = 7; k <= 12; ++k) a[k] = fmaxf(a[k], swr[w][k]);
        }
        #pragma unroll
        for (int k = 0; k < 13; ++k) d_red[blockIdx.x][k] = a[k];
    }
    grid_barrier(0);

    __shared__ float sg[128*13];
    if (tid < 128) {
        #pragma unroll
        for (int k = 0; k < 13; ++k) sg[tid*13 + k] = d_red[tid][k];
    }
    __syncthreads();
    for (int s = 64; s >= 1; s >>= 1) {
        if (tid < s) {
            sg[tid*13+0] = fmaxf(sg[tid*13+0], sg[(tid+s)*13+0]);
            #pragma unroll
            for (int k = 1; k <= 6; ++k) sg[tid*13+k] = fminf(sg[tid*13+k], sg[(tid+s)*13+k]);
            #pragma unroll
            for (int k = 7; k <= 12; ++k) sg[tid*13+k] = fmaxf(sg[tid*13+k], sg[(tid+s)*13+k]);
        }
        __syncthreads();
    }
    const float s_scale = 1.f / (sqrtf(sg[0]) + 1e-6f);
    float eps1;
    {
        float e = 0.f;
        #pragma unroll
        for (int k = 0; k < 6; ++k) { float d = sg[7+k] - sg[1+k]; e += d * d; }
        eps1 = e;
    }
    const float inv_e1 = 1.f / eps1;

    // ---------- Phase B: build U/V + stage-0 moments ----------
    float u[6], sq;
    {
        const float* src = isx ? (x + (size_t)q*6) : (y + (size_t)q*6);
        float* dst = isx ? (d_U + (size_t)q*8) : (d_V + (size_t)q*8);
        u[0] = src[0]*s_scale; u[1] = src[1]*s_scale; u[2] = src[2]*s_scale;
        u[3] = 0.1f * fminf(fmaxf(src[3], 0.f), 1.f);
        u[4] = 0.1f * fminf(fmaxf(src[4], 0.f), 1.f);
        u[5] = 0.1f * fminf(fmaxf(src[5], 0.f), 1.f);
        sq = u[0]*u[0]+u[1]*u[1]+u[2]*u[2]+u[3]*u[3]+u[4]*u[4]+u[5]*u[5];
        reinterpret_cast<float4*>(dst)[0] = make_float4(u[0], u[1], u[2], u[3]);
        reinterpret_cast<float4*>(dst)[1] = make_float4(u[4], u[5], sq, 0.f);
    }
    float w6[6];
    #pragma unroll
    for (int k = 0; k < 6; ++k) w6[k] = 2.f * u[k] * inv_e1;
    {
        int seg0 = (isx ? 4 : 0) + b;
        float om = ex2(LOG2E * ((0.f - sq) * inv_e1 + BLOG));
        float acc[28];
        acc[0] = om;
        #pragma unroll
        for (int k = 0; k < 6; ++k) acc[1+k] = om * w6[k];
        int cnt = 7;
        #pragma unroll
        for (int k = 0; k < 6; ++k)
            #pragma unroll
            for (int l = k; l < 6; ++l) acc[cnt++] = acc[1+k] * w6[l];
        reduce28_atomic(acc, d_M0 + seg0*32);
    }
    grid_barrier(1);

    // ---------- Phase P0: f0/g0 + stage-1 moments ----------
    const int dir = isx ? 0 : 1;
    {
        int rowseg = dir*4 + b;
        float S = eval_poly(d_M0 + rowseg*32, u);
        float val = sq - eps1 * (LN2F * lg2(S));
        if (dir == 0) d_f[0][q] = val; else d_g[0][q] = val;
        float om = __fdividef(EBLOG, S);
        int colseg = (dir^1)*4 + b;
        float acc[28];
        acc[0] = om;
        #pragma unroll
        for (int k = 0; k < 6; ++k) acc[1+k] = om * w6[k];
        int cnt = 7;
        #pragma unroll
        for (int k = 0; k < 6; ++k)
            #pragma unroll
            for (int l = k; l < 6; ++l) acc[cnt++] = acc[1+k] * w6[l];
        reduce28_atomic(acc, d_M1 + colseg*32);
    }
    grid_barrier(2);

    // ---------- Phase P1: f1/g1 + pack eps2 columns -> Pbuf[0] ----------
    {
        int rowseg = dir*4 + b;
        float S = eval_poly(d_M1 + rowseg*32, u);
        float val = sq - eps1 * (LN2F * lg2(S));
        float prev = (dir == 0) ? d_f[0][q] : d_g[0][q];
        float res = 0.5f * (prev + val);
        if (dir == 0) d_f[1][q] = res; else d_g[1][q] = res;

        int colseg = (dir^1)*4 + b;
        float cw = 2.f * LOG2E / EPS2;
        float h2 = LOG2E * BLOG + (res - sq) * (LOG2E / EPS2);
        write_pack_pair(d_Pbuf + (size_t)colseg*NN*8, q & (NN-1), u, cw, h2);
    }
}

// ============ eps2 main: quad-j via SMEM stage, 4 rows/thread, 128-thread blocks ============
// grid = (32 rowtiles, 8 segs, 8 jchunks), block 128 (4 warps, each warp 64 j-pairs
// = 32 quads, 4KB smem slab). Longer loop amortizes the LDG prologue (~600cyc) that
// was ~27% of block lifetime at NCHUNK=16; also halves block count / staging traffic.
// Quad merged per R13/R15 scheme: sequential halves, hi = max of 4, one merge, <=64 regs.
__global__ void __launch_bounds__(128, 8) k_main(int srcpp) {
    const int seg = blockIdx.y;
    const int b = seg & 3;
    const int dir = seg >> 2;
    const float* Rows = (dir ? d_V : d_U) + (size_t)b*NN*8;
    const float* Pin  = d_Pbuf + (size_t)srcpp*PBUF + (size_t)seg*NN*8;

    const int lane = threadIdx.x & 31;
    const int warp = threadIdx.x >> 5;      // 0..3
    const int rowbase = blockIdx.x * 128;

    __shared__ __align__(16) float sP[4][1024];   // 4 warps x 64 pairs x 64B

    // stage this warp's 64 pairs (4KB) into shared: 256 float4, 8 per lane
    {
        const float4* src = reinterpret_cast<const float4*>(Pin)
                            + ((size_t)blockIdx.z*256 + (size_t)warp*64)*4;
        float4* dst = reinterpret_cast<float4*>(&sP[warp][0]);
        #pragma unroll
        for (int i = 0; i < 8; ++i) dst[lane + 32*i] = src[lane + 32*i];
    }

    // 4 rows per thread (lane, +32, +64, +96), each duplicated into f32x2 chains
    unsigned long long U[4][6];
    #pragma unroll
    for (int p = 0; p < 4; ++p) {
        const float4* ra = reinterpret_cast<const float4*>(Rows + (size_t)(rowbase + lane + 32*p)*8);
        float4 a0 = ra[0], a1 = ra[1];
        U[p][0] = pack2(a0.x, a0.x); U[p][1] = pack2(a0.y, a0.y); U[p][2] = pack2(a0.z, a0.z);
        U[p][3] = pack2(a0.w, a0.w); U[p][4] = pack2(a1.x, a1.x); U[p][5] = pack2(a1.y, a1.y);
    }
    __syncwarp();

    float m[4], s[4];
    #pragma unroll
    for (int p = 0; p < 4; ++p) { m[p] = NEG_INF; s[p] = 0.f; }

    const float* W = &sP[warp][0];
    #pragma unroll 2
    for (int it = 0; it < 32; ++it) {
        const float* Wp = W + it*32;            // quad = two consecutive pair records
        unsigned long long A[4];
        {   // half 1: first pair record (j0,j1)
            ulonglong2 q0 = *reinterpret_cast<const ulonglong2*>(Wp + 0);
            ulonglong2 q1 = *reinterpret_cast<const ulonglong2*>(Wp + 4);
            ulonglong2 q2 = *reinterpret_cast<const ulonglong2*>(Wp + 8);
            unsigned long long hp = *reinterpret_cast<const unsigned long long*>(Wp + 12);
            #pragma unroll
            for (int p = 0; p < 4; ++p) {
                unsigned long long A_;
                FMA2(A_, U[p][0], q0.x, hp);
                FMA2(A_, U[p][1], q0.y, A_);
                FMA2(A_, U[p][2], q1.x, A_);
                FMA2(A_, U[p][3], q1.y, A_);
                FMA2(A_, U[p][4], q2.x, A_);
                FMA2(A_, U[p][5], q2.y, A_);
                A[p] = A_;
            }
        }
        {   // half 2: second pair record (j2,j3), then merge per row
            ulonglong2 q0 = *reinterpret_cast<const ulonglong2*>(Wp + 16);
            ulonglong2 q1 = *reinterpret_cast<const ulonglong2*>(Wp + 20);
            ulonglong2 q2 = *reinterpret_cast<const ulonglong2*>(Wp + 24);
            unsigned long long hp = *reinterpret_cast<const unsigned long long*>(Wp + 28);
            #pragma unroll
            for (int p = 0; p < 4; ++p) {
                unsigned long long B_;
                FMA2(B_, U[p][0], q0.x, hp);
                FMA2(B_, U[p][1], q0.y, B_);
                FMA2(B_, U[p][2], q1.x, B_);
                FMA2(B_, U[p][3], q1.y, B_);
                FMA2(B_, U[p][4], q2.x, B_);
                FMA2(B_, U[p][5], q2.y, B_);
                // hi of quad -> single streaming logsumexp merge
                float x1, x2, x3, x4;
                unpack2(x1, x2, A[p]); unpack2(x3, x4, B_);
                float hi = fmaxf(fmaxf(x1, x2), fmaxf(x3, x4));
                float d  = hi - m[p];
                float e  = ex2(-fabsf(d));
                bool up_ = d > 0.f;
                s[p] = up_ ? fmaf(s[p], e, 1.f) : (s[p] + e);
                m[p] = fmaxf(m[p], hi);
            }
        }
    }

    __shared__ float shA[4][128];
    __shared__ float shB[4][128];
    #pragma unroll
    for (int p = 0; p < 4; ++p) {
        shA[warp][lane + 32*p] = m[p];
        shB[warp][lane + 32*p] = s[p];
    }
    __syncthreads();

    {
        const int t = threadIdx.x;          // 0..127, one row each
        float M = shA[0][t];
        #pragma unroll
        for (int w = 1; w < 4; ++w) M = fmaxf(M, shA[w][t]);
        float S = 0.f;
        #pragma unroll
        for (int w = 0; w < 4; ++w) S += shB[w][t] * ex2(shA[w][t] - M);
        d_part[((size_t)(seg << 12) + rowbase + t)*NCHUNK + blockIdx.z] = make_float2(M, S);
    }
}

// ============ merge partials -> potential update (+ next pack | + final partial sum) ============
template<bool HASNEXT>
__global__ void __launch_bounds__(256) k_merge(int cur, int dstpp, float alpha, float beta) {
    const int p = blockIdx.x * 256 + threadIdx.x;    // 0..32767
    const int seg = p >> 12;
    const int r = p & 4095;
    const int dir = seg >> 2;
    const int b = seg & 3;
    const int q = b*NN + r;

    float2 c[NCHUNK];
    #pragma unroll
    for (int k = 0; k < NCHUNK; ++k) c[k] = d_part[(size_t)p*NCHUNK + k];
    float M = c[0].x;
    #pragma unroll
    for (int k = 1; k < NCHUNK; ++k) M = fmaxf(M, c[k].x);
    float S = 0.f;
    #pragma unroll
    for (int k = 0; k < NCHUNK; ++k) S += c[k].y * ex2(c[k].x - M);

    const float* src = (dir ? d_V : d_U) + (size_t)q*8;
    float sq = src[6];
    float val = sq - EPS2 * LN2F * (M + lg2(S));
    if (HASNEXT) {
        float fin = (dir ? d_g[cur][q] : d_f[cur][q]);
        float res = fmaf(alpha, fin, beta * val);
        if (dir == 0) d_f[cur^1][q] = res; else d_g[cur^1][q] = res;
        float u[6];
        u[0]=src[0]; u[1]=src[1]; u[2]=src[2]; u[3]=src[3]; u[4]=src[4]; u[5]=src[5];
        float cw = 2.f * LOG2E / EPS2;
        float h2 = LOG2E * BLOG + (res - sq) * (LOG2E / EPS2);
        write_pack_pair(d_Pbuf + (size_t)dstpp*PBUF + (size_t)((dir^1)*4 + b)*NN*8, r, u, cw, h2);
    } else {
        // final stage: pure softmin; deterministic block partial-sum
        float sum = val;
        #pragma unroll
        for (int o = 16; o; o >>= 1) sum += __shfl_xor_sync(0xffffffffu, sum, o);
        __shared__ float sw[8];
        int lane = threadIdx.x & 31, w = threadIdx.x >> 5;
        if (lane == 0) sw[w] = sum;
        __syncthreads();
        if (threadIdx.x == 0) {
            float t = 0.f;
            #pragma unroll
            for (int wi = 0; wi < 8; ++wi) t += sw[wi];
            d_osum[blockIdx.x] = t;
        }
    }
}

// ============ final: sum 128 block partials ============
__global__ void k_out(float* __restrict__ out) {
    const int tid = threadIdx.x;           // 128 threads
    float v = d_osum[tid];
    #pragma unroll
    for (int o = 16; o; o >>= 1) v += __shfl_xor_sync(0xffffffffu, v, o);
    __shared__ float sw[4];
    if ((tid & 31) == 0) sw[tid >> 5] = v;
    __syncthreads();
    if (tid == 0) out[0] = (sw[0] + sw[1] + sw[2] + sw[3]) * (10.f / (float)NPTS);
}

extern "C" void kernel_launch(void* const* d_in, const int* in_sizes, int n_in,
                              void* d_out, int out_size) {
    (void)in_sizes; (void)n_in; (void)out_size;
    const float* x = (const float*)d_in[0];
    const float* y = (const float*)d_in[1];
    float* out = (float*)d_out;

    dim3 gm(32, 8, NCHUNK);
    k_pre<<<NBLK, 256>>>(x, y);                        // f1/g1 + Pbuf[0]
    k_main<<<gm, 128>>>(0);                            // stage2 partials
    k_merge<true ><<<NBLK, 256>>>(1, 1, 0.5f, 0.5f);   // f2/g2 -> idx0, pack Pbuf[1]
    k_main<<<gm, 128>>>(1);                            // stage3 partials
    k_merge<false><<<NBLK, 256>>>(0, 0, 0.0f, 1.0f);   // f_new/g_new + block sums
    k_out<<<1, 128>>>(out);
}